// round 15
// baseline (speedup 1.0000x reference)
#include <cuda_runtime.h>
#include <cuda_bf16.h>
#include <cstdint>
typedef unsigned long long ull;

#define S_ 64
#define B_ 64
#define H_ 512
#define V_ 32000
#define NCTA 128

// ---------------- device scratch ----------------
__device__ __align__(16) float g_x[S_ * B_ * 512];
__device__ __align__(16) float g_hall[S_ * B_ * 512];
__device__ __align__(16) float g_h[2][2 * B_ * 512];
__device__ __align__(16) float g_wgT[2][1024 * 1024];
__device__ __align__(16) float g_wcT[2][512 * 1024];
__device__ __align__(16) ull g_partG[16 * 32768];
__device__ __align__(16) ull g_partC[32 * 16384];
__device__ __align__(128) unsigned g_flags[NCTA];
__device__ __align__(16) __nv_bfloat16 g_AH[4096 * 512];
__device__ __align__(16) __nv_bfloat16 g_AL[4096 * 512];
__device__ __align__(16) __nv_bfloat16 g_BTH[32000 * 512];   // Wout^T hi  [n][k]
__device__ __align__(16) __nv_bfloat16 g_BTL[32000 * 512];   // Wout^T lo  [n][k]

__device__ __forceinline__ ull pack2(float lo, float hi) {
    ull r; asm("mov.b64 %0, {%1, %2};" : "=l"(r) : "f"(lo), "f"(hi)); return r;
}
__device__ __forceinline__ void ffma2(ull& d, ull a, ull b) {
    asm("fma.rn.f32x2 %0, %1, %2, %0;" : "+l"(d) : "l"(a), "l"(b));
}
__device__ __forceinline__ void addf2(ull& d, ull a) {
    asm("add.rn.f32x2 %0, %0, %1;" : "+l"(d) : "l"(a));
}
__device__ __forceinline__ float2 unpack2(ull v) {
    float lo, hi; asm("mov.b64 {%0, %1}, %2;" : "=f"(lo), "=f"(hi) : "l"(v));
    return make_float2(lo, hi);
}
__device__ __forceinline__ float sigm(float x) { return 1.f / (1.f + __expf(-x)); }

__device__ __forceinline__ uint32_t smem_u32(const void* p) {
    uint32_t a;
    asm("{ .reg .u64 t; cvta.to.shared.u64 t, %1; cvt.u32.u64 %0, t; }" : "=r"(a) : "l"(p));
    return a;
}

// ---------------- small kernels ----------------
__global__ void reset_bar() {
    if (threadIdx.x < NCTA) g_flags[threadIdx.x] = 0u;
}

__global__ void embed_kernel(const int* __restrict__ tokens, const float* __restrict__ emb) {
    int idx = blockIdx.x * blockDim.x + threadIdx.x;
    int sb = idx >> 7, e4 = (idx & 127) * 4;
    *(float4*)&g_x[sb * 512 + e4] = *(const float4*)&emb[(size_t)tokens[sb] * 512 + e4];
}
__global__ void init_hidden(const float* __restrict__ src) {
    int i = blockIdx.x * blockDim.x + threadIdx.x; g_h[0][i] = src[i];
}
__global__ void copy_hidden(float* __restrict__ dst) {
    int i = blockIdx.x * blockDim.x + threadIdx.x; dst[i] = g_h[0][i];
}

__global__ __launch_bounds__(256) void pack_weights(const float* __restrict__ Wr,
                                                    const float* __restrict__ Wz,
                                                    const float* __restrict__ Wh) {
    __shared__ float t[32][33];
    int z = blockIdx.z, jt = blockIdx.y * 32, kt = blockIdx.x * 32;
    int tx = threadIdx.x & 31, ty = threadIdx.x >> 5;
    const float* base; float* outp; int jcol;
    if (z < 2) {
        base = (jt < 512) ? (Wr + z * 1024 * 512) : (Wz + z * 1024 * 512);
        jcol = (jt < 512) ? jt : jt - 512;
        outp = g_wgT[z];
    } else {
        if (jt >= 512) return;
        base = Wh + (z - 2) * 1024 * 512; jcol = jt; outp = g_wcT[z - 2];
    }
    #pragma unroll
    for (int r = 0; r < 4; ++r)
        t[ty + r * 8][tx] = base[(kt + ty + r * 8) * 512 + jcol + tx];
    __syncthreads();
    #pragma unroll
    for (int r = 0; r < 4; ++r) {
        int jl = ty + r * 8;
        outp[(jt + jl) * 1024 + kt + tx] = t[tx][jl];
    }
}

__global__ __launch_bounds__(256) void convert_woutT(const float* __restrict__ Wout) {
    __shared__ float t[32][33];
    int nt = blockIdx.x * 32, kt = blockIdx.y * 32;
    int tx = threadIdx.x & 31, ty = threadIdx.x >> 5;
    #pragma unroll
    for (int r = 0; r < 4; ++r)
        t[ty + r * 8][tx] = Wout[(size_t)(kt + ty + r * 8) * V_ + nt + tx];
    __syncthreads();
    #pragma unroll
    for (int r = 0; r < 4; ++r) {
        int nl = ty + r * 8;
        float v = t[tx][nl];
        __nv_bfloat16 h = __float2bfloat16(v);
        float lo = v - __bfloat162float(h);
        g_BTH[(size_t)(nt + nl) * 512 + kt + tx] = h;
        g_BTL[(size_t)(nt + nl) * 512 + kt + tx] = __float2bfloat16(lo);
    }
}

__global__ void convert_hall() {
    int idx = (blockIdx.x * blockDim.x + threadIdx.x) * 8;
    #pragma unroll
    for (int q = 0; q < 8; ++q) {
        float v = g_hall[idx + q];
        __nv_bfloat16 h = __float2bfloat16(v);
        g_AH[idx + q] = h;
        g_AL[idx + q] = __float2bfloat16(v - __bfloat162float(h));
    }
}

// ---------------- persistent recurrence ----------------
struct Shm {
    ull   A[32][34];
    float W[32][132];
};

// flag-array barrier: arrive = 1 release-store to own slot; wait = poll all slots
__device__ __forceinline__ void gsync(unsigned k) {
    __syncthreads();
    if (threadIdx.x == 0) {
        asm volatile("st.release.gpu.u32 [%0], %1;"
                     :: "l"(&g_flags[blockIdx.x]), "r"(k) : "memory");
    }
    if (threadIdx.x < NCTA) {
        unsigned v;
        do {
            asm volatile("ld.relaxed.gpu.u32 %0, [%1];"
                         : "=r"(v) : "l"(&g_flags[threadIdx.x]) : "memory");
        } while (v < k);
    }
    asm volatile("fence.acq_rel.gpu;" ::: "memory");
    __syncthreads();
}

__device__ __forceinline__ void stageA_plain(Shm* sm, int tid,
                                             const float* __restrict__ src, int koff) {
    int kq = (tid & 7) * 4, bps = tid >> 3;
    const float* p0 = src + (2 * bps) * 512 + koff + kq;
    float4 a0 = *(const float4*)p0;
    float4 a1 = *(const float4*)(p0 + 512);
    sm->A[kq + 0][bps] = pack2(a0.x, a1.x);
    sm->A[kq + 1][bps] = pack2(a0.y, a1.y);
    sm->A[kq + 2][bps] = pack2(a0.z, a1.z);
    sm->A[kq + 3][bps] = pack2(a0.w, a1.w);
}

__device__ __forceinline__ void stageA_rh(Shm* sm, int tid,
                                          const float* __restrict__ hold, int koff,
                                          const float* __restrict__ brl) {
    int kq = (tid & 7) * 4, bps = tid >> 3;
    float r0[4], r1[4];
    #pragma unroll
    for (int q = 0; q < 4; ++q) {
        int j = koff + kq + q;
        size_t base = (size_t)(j >> 7) * 4096 + bps * 128 + (j & 127);
        ull t = 0;
        #pragma unroll
        for (int ks = 0; ks < 16; ++ks) addf2(t, g_partG[(size_t)ks * 32768 + base]);
        float2 v = unpack2(t);
        float bb = brl[j];
        r0[q] = sigm(v.x + bb);
        r1[q] = sigm(v.y + bb);
    }
    const float* hp = hold + (2 * bps) * 512 + koff + kq;
    float4 h0 = *(const float4*)hp;
    float4 h1 = *(const float4*)(hp + 512);
    sm->A[kq + 0][bps] = pack2(h0.x * r0[0], h1.x * r1[0]);
    sm->A[kq + 1][bps] = pack2(h0.y * r0[1], h1.y * r1[1]);
    sm->A[kq + 2][bps] = pack2(h0.z * r0[2], h1.z * r1[2]);
    sm->A[kq + 3][bps] = pack2(h0.w * r0[3], h1.w * r1[3]);
}

__device__ __forceinline__ void stageW(Shm* sm, int tid,
                                       const float* __restrict__ wT, int gc0, int kbase) {
    int colw = tid & 127, kw = (tid >> 7) * 16;
    const float* p = wT + (size_t)(gc0 + colw) * 1024 + kbase + kw;
    #pragma unroll
    for (int i = 0; i < 4; ++i) {
        float4 w = *(const float4*)(p + 4 * i);
        sm->W[kw + 4 * i + 0][colw] = w.x;
        sm->W[kw + 4 * i + 1][colw] = w.y;
        sm->W[kw + 4 * i + 2][colw] = w.z;
        sm->W[kw + 4 * i + 3][colw] = w.w;
    }
}

__device__ __forceinline__ void storeA_regs(Shm* sm, int tid,
                                            const float4& a0, const float4& a1) {
    int kq = (tid & 7) * 4, bps = tid >> 3;
    sm->A[kq + 0][bps] = pack2(a0.x, a1.x);
    sm->A[kq + 1][bps] = pack2(a0.y, a1.y);
    sm->A[kq + 2][bps] = pack2(a0.z, a1.z);
    sm->A[kq + 3][bps] = pack2(a0.w, a1.w);
}
__device__ __forceinline__ void storeW_regs(Shm* sm, int tid, const float4* w) {
    int colw = tid & 127, kw = (tid >> 7) * 16;
    #pragma unroll
    for (int i = 0; i < 4; ++i) {
        sm->W[kw + 4 * i + 0][colw] = w[i].x;
        sm->W[kw + 4 * i + 1][colw] = w[i].y;
        sm->W[kw + 4 * i + 2][colw] = w[i].z;
        sm->W[kw + 4 * i + 3][colw] = w[i].w;
    }
}

__device__ __forceinline__ void inner32(Shm* sm, int bp0, int col0, ull* acc) {
    #pragma unroll 4
    for (int k = 0; k < 32; ++k) {
        ulonglong2 a01 = *(const ulonglong2*)&sm->A[k][bp0];
        ulonglong2 a23 = *(const ulonglong2*)&sm->A[k][bp0 + 2];
        float4 w = *(const float4*)&sm->W[k][col0];
        ull w0 = pack2(w.x, w.x), w1 = pack2(w.y, w.y);
        ull w2 = pack2(w.z, w.z), w3 = pack2(w.w, w.w);
        ffma2(acc[0],  a01.x, w0); ffma2(acc[1],  a01.x, w1);
        ffma2(acc[2],  a01.x, w2); ffma2(acc[3],  a01.x, w3);
        ffma2(acc[4],  a01.y, w0); ffma2(acc[5],  a01.y, w1);
        ffma2(acc[6],  a01.y, w2); ffma2(acc[7],  a01.y, w3);
        ffma2(acc[8],  a23.x, w0); ffma2(acc[9],  a23.x, w1);
        ffma2(acc[10], a23.x, w2); ffma2(acc[11], a23.x, w3);
        ffma2(acc[12], a23.y, w0); ffma2(acc[13], a23.y, w1);
        ffma2(acc[14], a23.y, w2); ffma2(acc[15], a23.y, w3);
    }
}

__device__ __forceinline__ void store_partials(ull* __restrict__ out,
                                               int bp0, int col0, const ull* acc) {
    #pragma unroll
    for (int i = 0; i < 4; ++i) {
        ulonglong2* q = (ulonglong2*)&out[(bp0 + i) * 128 + col0];
        q[0] = make_ulonglong2(acc[i * 4 + 0], acc[i * 4 + 1]);
        q[1] = make_ulonglong2(acc[i * 4 + 2], acc[i * 4 + 3]);
    }
}

// gates partial with chunk-1 prefetch (both chunks of a k-slice use the same src)
__device__ void gatesP(Shm* sm, int cta, int tid, int l,
                       const float* __restrict__ inp, const float* __restrict__ hold) {
    int tile = cta >> 4, ks = cta & 15;
    int gc0 = tile * 128;
    int bp0 = (tid & 7) * 4, col0 = (tid >> 3) * 4;
    int kbase0 = ks * 64, kbase1 = kbase0 + 32;
    const float* src = (kbase0 < 512) ? inp : hold;
    int koff0 = kbase0 & 511, koff1 = kbase1 & 511;

    ull acc[16];
    #pragma unroll
    for (int i = 0; i < 16; ++i) acc[i] = 0;

    // chunk 0 stage
    stageA_plain(sm, tid, src, koff0);
    stageW(sm, tid, g_wgT[l], gc0, kbase0);
    // prefetch chunk 1 into registers (hidden under inner32 chunk 0)
    int kq = (tid & 7) * 4, bps = tid >> 3;
    const float* pA1 = src + (2 * bps) * 512 + koff1 + kq;
    float4 a1_0 = *(const float4*)pA1;
    float4 a1_1 = *(const float4*)(pA1 + 512);
    float4 w1[4];
    {
        int colw = tid & 127, kw = (tid >> 7) * 16;
        const float* pW1 = g_wgT[l] + (size_t)(gc0 + colw) * 1024 + kbase1 + kw;
        #pragma unroll
        for (int i = 0; i < 4; ++i) w1[i] = *(const float4*)(pW1 + 4 * i);
    }
    __syncthreads();
    inner32(sm, bp0, col0, acc);
    __syncthreads();
    storeA_regs(sm, tid, a1_0, a1_1);
    storeW_regs(sm, tid, w1);
    __syncthreads();
    inner32(sm, bp0, col0, acc);

    store_partials(g_partG + (size_t)ks * 32768 + tile * 4096, bp0, col0, acc);
}

__device__ void candP(Shm* sm, int cta, int tid, int l,
                      const float* __restrict__ inp, const float* __restrict__ hold,
                      const float* __restrict__ brl) {
    int tile = cta >> 5, ks = cta & 31;
    int gc0 = tile * 128;
    int kbase = ks * 32;
    int bp0 = (tid & 7) * 4, col0 = (tid >> 3) * 4;
    ull acc[16];
    #pragma unroll
    for (int i = 0; i < 16; ++i) acc[i] = 0;
    if (kbase < 512) stageA_plain(sm, tid, inp, kbase);
    else             stageA_rh(sm, tid, hold, kbase - 512, brl);
    stageW(sm, tid, g_wcT[l], gc0, kbase);
    __syncthreads();
    inner32(sm, bp0, col0, acc);
    store_partials(g_partC + (size_t)ks * 16384 + tile * 4096, bp0, col0, acc);
}

__device__ void candR(int cta, int tid, const float* __restrict__ bhl,
                      const float* __restrict__ bzl,
                      const float* __restrict__ hold, float* __restrict__ hnew, int s) {
    if (tid < 128) {
        int o = cta * 128 + tid;
        ull t = 0;
        #pragma unroll
        for (int ks = 0; ks < 32; ++ks) addf2(t, g_partC[(size_t)ks * 16384 + o]);
        int tile = o >> 12, bp = (o >> 7) & 31, colL = o & 127;
        int j = tile * 128 + colL, b0 = 2 * bp;
        size_t zbase = (size_t)(4 + (j >> 7)) * 4096 + bp * 128 + (j & 127);
        ull zt = 0;
        #pragma unroll
        for (int ks = 0; ks < 16; ++ks) addf2(zt, g_partG[(size_t)ks * 32768 + zbase]);
        float2 zv = unpack2(zt);
        float zb = bzl[j];
        float z0 = sigm(zv.x + zb), z1 = sigm(zv.y + zb);
        float2 v = unpack2(t);
        float bb = bhl[j];
        float hh0 = tanhf(v.x + bb), hh1 = tanhf(v.y + bb);
        float nh0 = (1.f - z0) * hold[b0 * 512 + j] + z0 * hh0;
        float nh1 = (1.f - z1) * hold[(b0 + 1) * 512 + j] + z1 * hh1;
        hnew[b0 * 512 + j]       = nh0;
        hnew[(b0 + 1) * 512 + j] = nh1;
        if (s >= 0) {
            g_hall[(s * 64 + b0) * 512 + j]     = nh0;
            g_hall[(s * 64 + b0 + 1) * 512 + j] = nh1;
        }
    }
}

__global__ __launch_bounds__(256, 1) void gru_persistent(const float* __restrict__ br,
                                                         const float* __restrict__ bz,
                                                         const float* __restrict__ bh) {
    __shared__ Shm sm;
    const int tid = threadIdx.x, cta = blockIdx.x;
    unsigned sid = 0; int p = 0;
    for (int s = 0; s < S_; ++s) {
        const float* x_t = g_x + s * B_ * 512;
        float* hOld = g_h[p];
        float* hNew = g_h[1 - p];
        #pragma unroll
        for (int l = 0; l < 2; ++l) {
            const float* inp  = l ? hNew : x_t;
            const float* hold = hOld + l * B_ * H_;
            float* hn = hNew + l * B_ * H_;
            gatesP(&sm, cta, tid, l, inp, hold);
            gsync(++sid);
            candP(&sm, cta, tid, l, inp, hold, br + l * 512);
            gsync(++sid);
            candR(cta, tid, bh + l * 512, bz + l * 512, hold, hn, (l == 1) ? s : -1);
            gsync(++sid);
        }
        p ^= 1;
    }
}

// ---------------- HMMA bf16-split output GEMM (unchanged from R12) ----------------
#define LDM_X4(r0, r1, r2, r3, a) \
    asm volatile("ldmatrix.sync.aligned.m8n8.x4.shared.b16 {%0,%1,%2,%3}, [%4];" \
        : "=r"(r0), "=r"(r1), "=r"(r2), "=r"(r3) : "r"(a))
#define LDM_X2(r0, r1, a) \
    asm volatile("ldmatrix.sync.aligned.m8n8.x2.shared.b16 {%0,%1}, [%2];" \
        : "=r"(r0), "=r"(r1) : "r"(a))
#define MMA_BF16(c, a, b) \
    asm volatile("mma.sync.aligned.m16n8k16.row.col.f32.bf16.bf16.f32 " \
        "{%0,%1,%2,%3}, {%4,%5,%6,%7}, {%8,%9}, {%0,%1,%2,%3};" \
        : "+f"((c)[0]), "+f"((c)[1]), "+f"((c)[2]), "+f"((c)[3]) \
        : "r"((a)[0]), "r"((a)[1]), "r"((a)[2]), "r"((a)[3]), "r"((b)[0]), "r"((b)[1]))

__global__ __launch_bounds__(256) void out_gemm_hmma(const float* __restrict__ bout,
                                                     float* __restrict__ C) {
    __shared__ __align__(16) __nv_bfloat16 sA[2][128][40];
    __shared__ __align__(16) __nv_bfloat16 sB[2][128][40];

    const int tid = threadIdx.x, wid = tid >> 5, lane = tid & 31;
    const int m0 = blockIdx.x * 128, n0 = blockIdx.y * 128;
    const int wm = wid & 3, wn = wid >> 2;

    float acc[2][8][4];
    #pragma unroll
    for (int mt = 0; mt < 2; ++mt)
        #pragma unroll
        for (int nt = 0; nt < 8; ++nt)
            #pragma unroll
            for (int q = 0; q < 4; ++q) acc[mt][nt][q] = 0.f;

    const int sr = tid >> 1, seg = tid & 1;

    for (int kc = 0; kc < 16; ++kc) {
        {
            const uint4* pAh = (const uint4*)(g_AH + (size_t)(m0 + sr) * 512 + kc * 32 + seg * 16);
            const uint4* pAl = (const uint4*)(g_AL + (size_t)(m0 + sr) * 512 + kc * 32 + seg * 16);
            const uint4* pBh = (const uint4*)(g_BTH + (size_t)(n0 + sr) * 512 + kc * 32 + seg * 16);
            const uint4* pBl = (const uint4*)(g_BTL + (size_t)(n0 + sr) * 512 + kc * 32 + seg * 16);
            uint4* qAh = (uint4*)&sA[0][sr][seg * 16];
            uint4* qAl = (uint4*)&sA[1][sr][seg * 16];
            uint4* qBh = (uint4*)&sB[0][sr][seg * 16];
            uint4* qBl = (uint4*)&sB[1][sr][seg * 16];
            qAh[0] = pAh[0]; qAh[1] = pAh[1];
            qAl[0] = pAl[0]; qAl[1] = pAl[1];
            qBh[0] = pBh[0]; qBh[1] = pBh[1];
            qBl[0] = pBl[0]; qBl[1] = pBl[1];
        }
        __syncthreads();
        #pragma unroll
        for (int ks = 0; ks < 2; ++ks) {
            uint32_t Ah[2][4], Al[2][4];
            #pragma unroll
            for (int mt = 0; mt < 2; ++mt) {
                uint32_t a0 = smem_u32(&sA[0][wm * 32 + mt * 16 + (lane & 15)][ks * 16 + (lane >> 4) * 8]);
                LDM_X4(Ah[mt][0], Ah[mt][1], Ah[mt][2], Ah[mt][3], a0);
                uint32_t a1 = smem_u32(&sA[1][wm * 32 + mt * 16 + (lane & 15)][ks * 16 + (lane >> 4) * 8]);
                LDM_X4(Al[mt][0], Al[mt][1], Al[mt][2], Al[mt][3], a1);
            }
            #pragma unroll
            for (int nt = 0; nt < 8; ++nt) {
                uint32_t Bh[2], Bl[2];
                uint32_t b0 = smem_u32(&sB[0][wn * 64 + nt * 8 + (lane & 7)][ks * 16 + ((lane >> 3) & 1) * 8]);
                LDM_X2(Bh[0], Bh[1], b0);
                uint32_t b1 = smem_u32(&sB[1][wn * 64 + nt * 8 + (lane & 7)][ks * 16 + ((lane >> 3) & 1) * 8]);
                LDM_X2(Bl[0], Bl[1], b1);
                #pragma unroll
                for (int mt = 0; mt < 2; ++mt) {
                    MMA_BF16(acc[mt][nt], Ah[mt], Bh);
                    MMA_BF16(acc[mt][nt], Ah[mt], Bl);
                    MMA_BF16(acc[mt][nt], Al[mt], Bh);
                }
            }
        }
        __syncthreads();
    }

    #pragma unroll
    for (int nt = 0; nt < 8; ++nt) {
        int n = n0 + wn * 64 + nt * 8 + (lane & 3) * 2;
        float2 bv = *(const float2*)&bout[n];
        #pragma unroll
        for (int mt = 0; mt < 2; ++mt) {
            int m = m0 + wm * 32 + mt * 16 + (lane >> 2);
            float2 v0 = make_float2(acc[mt][nt][0] + bv.x, acc[mt][nt][1] + bv.y);
            float2 v1 = make_float2(acc[mt][nt][2] + bv.x, acc[mt][nt][3] + bv.y);
            *(float2*)&C[(size_t)m * V_ + n] = v0;
            *(float2*)&C[(size_t)(m + 8) * V_ + n] = v1;
        }
    }
}

// ---------------- launch ----------------
extern "C" void kernel_launch(void* const* d_in, const int* in_sizes, int n_in,
                              void* d_out, int out_size) {
    const int*   tokens = (const int*)d_in[0];
    const float* hidden = (const float*)d_in[1];
    const float* emb    = (const float*)d_in[2];
    const float* Wr     = (const float*)d_in[3];
    const float* br     = (const float*)d_in[4];
    const float* Wz     = (const float*)d_in[5];
    const float* bz     = (const float*)d_in[6];
    const float* Wh     = (const float*)d_in[7];
    const float* bh     = (const float*)d_in[8];
    const float* Wout   = (const float*)d_in[9];
    const float* bout   = (const float*)d_in[10];
    float* out = (float*)d_out;

    reset_bar<<<1, 128>>>();
    embed_kernel<<<2048, 256>>>(tokens, emb);
    init_hidden<<<256, 256>>>(hidden);
    pack_weights<<<dim3(32, 32, 4), 256>>>(Wr, Wz, Wh);
    convert_woutT<<<dim3(1000, 16), 256>>>(Wout);
    gru_persistent<<<NCTA, 256>>>(br, bz, bh);
    convert_hall<<<1024, 256>>>();
    out_gemm_hmma<<<dim3(32, 250), 256>>>(bout, out);
    copy_hidden<<<256, 256>>>(out + (size_t)S_ * B_ * V_);
}

// round 16
// speedup vs baseline: 1.5215x; 1.5215x over previous
#include <cuda_runtime.h>
#include <cuda_bf16.h>
#include <cstdint>
typedef unsigned long long ull;

#define S_ 64
#define B_ 64
#define H_ 512
#define V_ 32000
#define NCTA 128

// ---------------- device scratch ----------------
__device__ __align__(16) float g_x[S_ * B_ * 512];
__device__ __align__(16) float g_hall[S_ * B_ * 512];
__device__ __align__(16) float g_h[2][2 * B_ * 512];
__device__ __align__(16) float g_wgT[2][1024 * 1024];
__device__ __align__(16) float g_wcT[2][512 * 1024];
__device__ __align__(16) ull g_partG[16 * 32768];
__device__ __align__(16) ull g_partC[32 * 16384];
__device__ unsigned g_arrive, g_release;
__device__ __align__(16) __nv_bfloat16 g_AH[4096 * 512];
__device__ __align__(16) __nv_bfloat16 g_AL[4096 * 512];
__device__ __align__(16) __nv_bfloat16 g_BTH[32000 * 512];   // Wout^T hi  [n][k]
__device__ __align__(16) __nv_bfloat16 g_BTL[32000 * 512];   // Wout^T lo  [n][k]

__device__ __forceinline__ ull pack2(float lo, float hi) {
    ull r; asm("mov.b64 %0, {%1, %2};" : "=l"(r) : "f"(lo), "f"(hi)); return r;
}
__device__ __forceinline__ void ffma2(ull& d, ull a, ull b) {
    asm("fma.rn.f32x2 %0, %1, %2, %0;" : "+l"(d) : "l"(a), "l"(b));
}
__device__ __forceinline__ void addf2(ull& d, ull a) {
    asm("add.rn.f32x2 %0, %0, %1;" : "+l"(d) : "l"(a));
}
__device__ __forceinline__ float2 unpack2(ull v) {
    float lo, hi; asm("mov.b64 {%0, %1}, %2;" : "=f"(lo), "=f"(hi) : "l"(v));
    return make_float2(lo, hi);
}
__device__ __forceinline__ float sigm(float x) { return 1.f / (1.f + __expf(-x)); }

__device__ __forceinline__ uint32_t smem_u32(const void* p) {
    uint32_t a;
    asm("{ .reg .u64 t; cvta.to.shared.u64 t, %1; cvt.u32.u64 %0, t; }" : "=r"(a) : "l"(p));
    return a;
}

// ---------------- small kernels ----------------
__global__ void reset_bar() { g_arrive = 0u; g_release = 0u; }

__global__ void embed_kernel(const int* __restrict__ tokens, const float* __restrict__ emb) {
    int idx = blockIdx.x * blockDim.x + threadIdx.x;
    int sb = idx >> 7, e4 = (idx & 127) * 4;
    *(float4*)&g_x[sb * 512 + e4] = *(const float4*)&emb[(size_t)tokens[sb] * 512 + e4];
}
__global__ void init_hidden(const float* __restrict__ src) {
    int i = blockIdx.x * blockDim.x + threadIdx.x; g_h[0][i] = src[i];
}
__global__ void copy_hidden(float* __restrict__ dst) {
    int i = blockIdx.x * blockDim.x + threadIdx.x; dst[i] = g_h[0][i];
}

__global__ __launch_bounds__(256) void pack_weights(const float* __restrict__ Wr,
                                                    const float* __restrict__ Wz,
                                                    const float* __restrict__ Wh) {
    __shared__ float t[32][33];
    int z = blockIdx.z, jt = blockIdx.y * 32, kt = blockIdx.x * 32;
    int tx = threadIdx.x & 31, ty = threadIdx.x >> 5;
    const float* base; float* outp; int jcol;
    if (z < 2) {
        base = (jt < 512) ? (Wr + z * 1024 * 512) : (Wz + z * 1024 * 512);
        jcol = (jt < 512) ? jt : jt - 512;
        outp = g_wgT[z];
    } else {
        if (jt >= 512) return;
        base = Wh + (z - 2) * 1024 * 512; jcol = jt; outp = g_wcT[z - 2];
    }
    #pragma unroll
    for (int r = 0; r < 4; ++r)
        t[ty + r * 8][tx] = base[(kt + ty + r * 8) * 512 + jcol + tx];
    __syncthreads();
    #pragma unroll
    for (int r = 0; r < 4; ++r) {
        int jl = ty + r * 8;
        outp[(jt + jl) * 1024 + kt + tx] = t[tx][jl];
    }
}

__global__ __launch_bounds__(256) void convert_woutT(const float* __restrict__ Wout) {
    __shared__ float t[32][33];
    int nt = blockIdx.x * 32, kt = blockIdx.y * 32;
    int tx = threadIdx.x & 31, ty = threadIdx.x >> 5;
    #pragma unroll
    for (int r = 0; r < 4; ++r)
        t[ty + r * 8][tx] = Wout[(size_t)(kt + ty + r * 8) * V_ + nt + tx];
    __syncthreads();
    #pragma unroll
    for (int r = 0; r < 4; ++r) {
        int nl = ty + r * 8;
        float v = t[tx][nl];
        __nv_bfloat16 h = __float2bfloat16(v);
        float lo = v - __bfloat162float(h);
        g_BTH[(size_t)(nt + nl) * 512 + kt + tx] = h;
        g_BTL[(size_t)(nt + nl) * 512 + kt + tx] = __float2bfloat16(lo);
    }
}

// ---------------- persistent recurrence (R12 version, verbatim) ----------------
struct Shm {
    ull   A[32][34];
    float W[32][132];
};

__device__ __forceinline__ void gsync(unsigned k) {
    __syncthreads();
    if (threadIdx.x == 0) {
        __threadfence();
        unsigned t = atomicAdd(&g_arrive, 1u) + 1u;
        if (t == k * NCTA) {
            atomicExch(&g_release, k);
        } else {
            unsigned v;
            do {
                asm volatile("ld.acquire.gpu.u32 %0, [%1];"
                             : "=r"(v) : "l"(&g_release) : "memory");
            } while (v < k);
        }
    }
    __syncthreads();
}

__device__ __forceinline__ void stageA_plain(Shm* sm, int tid,
                                             const float* __restrict__ src, int koff) {
    int kq = (tid & 7) * 4, bps = tid >> 3;
    const float* p0 = src + (2 * bps) * 512 + koff + kq;
    float4 a0 = *(const float4*)p0;
    float4 a1 = *(const float4*)(p0 + 512);
    sm->A[kq + 0][bps] = pack2(a0.x, a1.x);
    sm->A[kq + 1][bps] = pack2(a0.y, a1.y);
    sm->A[kq + 2][bps] = pack2(a0.z, a1.z);
    sm->A[kq + 3][bps] = pack2(a0.w, a1.w);
}

__device__ __forceinline__ void stageA_rh(Shm* sm, int tid,
                                          const float* __restrict__ hold, int koff,
                                          const float* __restrict__ brl) {
    int kq = (tid & 7) * 4, bps = tid >> 3;
    float r0[4], r1[4];
    #pragma unroll
    for (int q = 0; q < 4; ++q) {
        int j = koff + kq + q;
        size_t base = (size_t)(j >> 7) * 4096 + bps * 128 + (j & 127);
        ull t = 0;
        #pragma unroll
        for (int ks = 0; ks < 16; ++ks) addf2(t, g_partG[(size_t)ks * 32768 + base]);
        float2 v = unpack2(t);
        float bb = brl[j];
        r0[q] = sigm(v.x + bb);
        r1[q] = sigm(v.y + bb);
    }
    const float* hp = hold + (2 * bps) * 512 + koff + kq;
    float4 h0 = *(const float4*)hp;
    float4 h1 = *(const float4*)(hp + 512);
    sm->A[kq + 0][bps] = pack2(h0.x * r0[0], h1.x * r1[0]);
    sm->A[kq + 1][bps] = pack2(h0.y * r0[1], h1.y * r1[1]);
    sm->A[kq + 2][bps] = pack2(h0.z * r0[2], h1.z * r1[2]);
    sm->A[kq + 3][bps] = pack2(h0.w * r0[3], h1.w * r1[3]);
}

__device__ __forceinline__ void stageW(Shm* sm, int tid,
                                       const float* __restrict__ wT, int gc0, int kbase) {
    int colw = tid & 127, kw = (tid >> 7) * 16;
    const float* p = wT + (size_t)(gc0 + colw) * 1024 + kbase + kw;
    #pragma unroll
    for (int i = 0; i < 4; ++i) {
        float4 w = *(const float4*)(p + 4 * i);
        sm->W[kw + 4 * i + 0][colw] = w.x;
        sm->W[kw + 4 * i + 1][colw] = w.y;
        sm->W[kw + 4 * i + 2][colw] = w.z;
        sm->W[kw + 4 * i + 3][colw] = w.w;
    }
}

__device__ __forceinline__ void inner32(Shm* sm, int bp0, int col0, ull* acc) {
    #pragma unroll 4
    for (int k = 0; k < 32; ++k) {
        ulonglong2 a01 = *(const ulonglong2*)&sm->A[k][bp0];
        ulonglong2 a23 = *(const ulonglong2*)&sm->A[k][bp0 + 2];
        float4 w = *(const float4*)&sm->W[k][col0];
        ull w0 = pack2(w.x, w.x), w1 = pack2(w.y, w.y);
        ull w2 = pack2(w.z, w.z), w3 = pack2(w.w, w.w);
        ffma2(acc[0],  a01.x, w0); ffma2(acc[1],  a01.x, w1);
        ffma2(acc[2],  a01.x, w2); ffma2(acc[3],  a01.x, w3);
        ffma2(acc[4],  a01.y, w0); ffma2(acc[5],  a01.y, w1);
        ffma2(acc[6],  a01.y, w2); ffma2(acc[7],  a01.y, w3);
        ffma2(acc[8],  a23.x, w0); ffma2(acc[9],  a23.x, w1);
        ffma2(acc[10], a23.x, w2); ffma2(acc[11], a23.x, w3);
        ffma2(acc[12], a23.y, w0); ffma2(acc[13], a23.y, w1);
        ffma2(acc[14], a23.y, w2); ffma2(acc[15], a23.y, w3);
    }
}

__device__ __forceinline__ void store_partials(ull* __restrict__ out,
                                               int bp0, int col0, const ull* acc) {
    #pragma unroll
    for (int i = 0; i < 4; ++i) {
        ulonglong2* q = (ulonglong2*)&out[(bp0 + i) * 128 + col0];
        q[0] = make_ulonglong2(acc[i * 4 + 0], acc[i * 4 + 1]);
        q[1] = make_ulonglong2(acc[i * 4 + 2], acc[i * 4 + 3]);
    }
}

__device__ void gatesP(Shm* sm, int cta, int tid, int l,
                       const float* __restrict__ inp, const float* __restrict__ hold) {
    int tile = cta >> 4, ks = cta & 15;
    int gc0 = tile * 128;
    int bp0 = (tid & 7) * 4, col0 = (tid >> 3) * 4;
    ull acc[16];
    #pragma unroll
    for (int i = 0; i < 16; ++i) acc[i] = 0;
    #pragma unroll
    for (int ch = 0; ch < 2; ++ch) {
        int kbase = ks * 64 + ch * 32;
        const float* src = (kbase < 512) ? inp : hold;
        stageA_plain(sm, tid, src, kbase & 511);
        stageW(sm, tid, g_wgT[l], gc0, kbase);
        __syncthreads();
        inner32(sm, bp0, col0, acc);
        __syncthreads();
    }
    store_partials(g_partG + (size_t)ks * 32768 + tile * 4096, bp0, col0, acc);
}

__device__ void candP(Shm* sm, int cta, int tid, int l,
                      const float* __restrict__ inp, const float* __restrict__ hold,
                      const float* __restrict__ brl) {
    int tile = cta >> 5, ks = cta & 31;
    int gc0 = tile * 128;
    int kbase = ks * 32;
    int bp0 = (tid & 7) * 4, col0 = (tid >> 3) * 4;
    ull acc[16];
    #pragma unroll
    for (int i = 0; i < 16; ++i) acc[i] = 0;
    if (kbase < 512) stageA_plain(sm, tid, inp, kbase);
    else             stageA_rh(sm, tid, hold, kbase - 512, brl);
    stageW(sm, tid, g_wcT[l], gc0, kbase);
    __syncthreads();
    inner32(sm, bp0, col0, acc);
    __syncthreads();
    store_partials(g_partC + (size_t)ks * 16384 + tile * 4096, bp0, col0, acc);
}

// cand reduce + z-reduce + tanh + blend; layer-1 also emits bf16 hi/lo for the GEMM
__device__ void candR(int cta, int tid, const float* __restrict__ bhl,
                      const float* __restrict__ bzl,
                      const float* __restrict__ hold, float* __restrict__ hnew, int s) {
    if (tid < 128) {
        int o = cta * 128 + tid;
        ull t = 0;
        #pragma unroll
        for (int ks = 0; ks < 32; ++ks) addf2(t, g_partC[(size_t)ks * 16384 + o]);
        int tile = o >> 12, bp = (o >> 7) & 31, colL = o & 127;
        int j = tile * 128 + colL, b0 = 2 * bp;
        size_t zbase = (size_t)(4 + (j >> 7)) * 4096 + bp * 128 + (j & 127);
        ull zt = 0;
        #pragma unroll
        for (int ks = 0; ks < 16; ++ks) addf2(zt, g_partG[(size_t)ks * 32768 + zbase]);
        float2 zv = unpack2(zt);
        float zb = bzl[j];
        float z0 = sigm(zv.x + zb), z1 = sigm(zv.y + zb);
        float2 v = unpack2(t);
        float bb = bhl[j];
        float hh0 = tanhf(v.x + bb), hh1 = tanhf(v.y + bb);
        float nh0 = (1.f - z0) * hold[b0 * 512 + j] + z0 * hh0;
        float nh1 = (1.f - z1) * hold[(b0 + 1) * 512 + j] + z1 * hh1;
        hnew[b0 * 512 + j]       = nh0;
        hnew[(b0 + 1) * 512 + j] = nh1;
        if (s >= 0) {
            size_t i0 = (size_t)(s * 64 + b0) * 512 + j;
            size_t i1 = i0 + 512;
            g_hall[i0] = nh0;
            g_hall[i1] = nh1;
            __nv_bfloat16 h0 = __float2bfloat16(nh0);
            __nv_bfloat16 h1 = __float2bfloat16(nh1);
            g_AH[i0] = h0;
            g_AH[i1] = h1;
            g_AL[i0] = __float2bfloat16(nh0 - __bfloat162float(h0));
            g_AL[i1] = __float2bfloat16(nh1 - __bfloat162float(h1));
        }
    }
}

__global__ __launch_bounds__(256, 1) void gru_persistent(const float* __restrict__ br,
                                                         const float* __restrict__ bz,
                                                         const float* __restrict__ bh) {
    __shared__ Shm sm;
    const int tid = threadIdx.x, cta = blockIdx.x;
    unsigned sid = 0; int p = 0;
    for (int s = 0; s < S_; ++s) {
        const float* x_t = g_x + s * B_ * 512;
        float* hOld = g_h[p];
        float* hNew = g_h[1 - p];
        #pragma unroll
        for (int l = 0; l < 2; ++l) {
            const float* inp  = l ? hNew : x_t;
            const float* hold = hOld + l * B_ * H_;
            float* hn = hNew + l * B_ * H_;
            gatesP(&sm, cta, tid, l, inp, hold);
            gsync(++sid);
            candP(&sm, cta, tid, l, inp, hold, br + l * 512);
            gsync(++sid);
            candR(cta, tid, bh + l * 512, bz + l * 512, hold, hn, (l == 1) ? s : -1);
            gsync(++sid);
        }
        p ^= 1;
    }
}

// ---------------- HMMA bf16-split output GEMM (unchanged from R12) ----------------
#define LDM_X4(r0, r1, r2, r3, a) \
    asm volatile("ldmatrix.sync.aligned.m8n8.x4.shared.b16 {%0,%1,%2,%3}, [%4];" \
        : "=r"(r0), "=r"(r1), "=r"(r2), "=r"(r3) : "r"(a))
#define LDM_X2(r0, r1, a) \
    asm volatile("ldmatrix.sync.aligned.m8n8.x2.shared.b16 {%0,%1}, [%2];" \
        : "=r"(r0), "=r"(r1) : "r"(a))
#define MMA_BF16(c, a, b) \
    asm volatile("mma.sync.aligned.m16n8k16.row.col.f32.bf16.bf16.f32 " \
        "{%0,%1,%2,%3}, {%4,%5,%6,%7}, {%8,%9}, {%0,%1,%2,%3};" \
        : "+f"((c)[0]), "+f"((c)[1]), "+f"((c)[2]), "+f"((c)[3]) \
        : "r"((a)[0]), "r"((a)[1]), "r"((a)[2]), "r"((a)[3]), "r"((b)[0]), "r"((b)[1]))

__global__ __launch_bounds__(256) void out_gemm_hmma(const float* __restrict__ bout,
                                                     float* __restrict__ C) {
    __shared__ __align__(16) __nv_bfloat16 sA[2][128][40];
    __shared__ __align__(16) __nv_bfloat16 sB[2][128][40];

    const int tid = threadIdx.x, wid = tid >> 5, lane = tid & 31;
    const int m0 = blockIdx.x * 128, n0 = blockIdx.y * 128;
    const int wm = wid & 3, wn = wid >> 2;

    float acc[2][8][4];
    #pragma unroll
    for (int mt = 0; mt < 2; ++mt)
        #pragma unroll
        for (int nt = 0; nt < 8; ++nt)
            #pragma unroll
            for (int q = 0; q < 4; ++q) acc[mt][nt][q] = 0.f;

    const int sr = tid >> 1, seg = tid & 1;

    for (int kc = 0; kc < 16; ++kc) {
        {
            const uint4* pAh = (const uint4*)(g_AH + (size_t)(m0 + sr) * 512 + kc * 32 + seg * 16);
            const uint4* pAl = (const uint4*)(g_AL + (size_t)(m0 + sr) * 512 + kc * 32 + seg * 16);
            const uint4* pBh = (const uint4*)(g_BTH + (size_t)(n0 + sr) * 512 + kc * 32 + seg * 16);
            const uint4* pBl = (const uint4*)(g_BTL + (size_t)(n0 + sr) * 512 + kc * 32 + seg * 16);
            uint4* qAh = (uint4*)&sA[0][sr][seg * 16];
            uint4* qAl = (uint4*)&sA[1][sr][seg * 16];
            uint4* qBh = (uint4*)&sB[0][sr][seg * 16];
            uint4* qBl = (uint4*)&sB[1][sr][seg * 16];
            qAh[0] = pAh[0]; qAh[1] = pAh[1];
            qAl[0] = pAl[0]; qAl[1] = pAl[1];
            qBh[0] = pBh[0]; qBh[1] = pBh[1];
            qBl[0] = pBl[0]; qBl[1] = pBl[1];
        }
        __syncthreads();
        #pragma unroll
        for (int ks = 0; ks < 2; ++ks) {
            uint32_t Ah[2][4], Al[2][4];
            #pragma unroll
            for (int mt = 0; mt < 2; ++mt) {
                uint32_t a0 = smem_u32(&sA[0][wm * 32 + mt * 16 + (lane & 15)][ks * 16 + (lane >> 4) * 8]);
                LDM_X4(Ah[mt][0], Ah[mt][1], Ah[mt][2], Ah[mt][3], a0);
                uint32_t a1 = smem_u32(&sA[1][wm * 32 + mt * 16 + (lane & 15)][ks * 16 + (lane >> 4) * 8]);
                LDM_X4(Al[mt][0], Al[mt][1], Al[mt][2], Al[mt][3], a1);
            }
            #pragma unroll
            for (int nt = 0; nt < 8; ++nt) {
                uint32_t Bh[2], Bl[2];
                uint32_t b0 = smem_u32(&sB[0][wn * 64 + nt * 8 + (lane & 7)][ks * 16 + ((lane >> 3) & 1) * 8]);
                LDM_X2(Bh[0], Bh[1], b0);
                uint32_t b1 = smem_u32(&sB[1][wn * 64 + nt * 8 + (lane & 7)][ks * 16 + ((lane >> 3) & 1) * 8]);
                LDM_X2(Bl[0], Bl[1], b1);
                #pragma unroll
                for (int mt = 0; mt < 2; ++mt) {
                    MMA_BF16(acc[mt][nt], Ah[mt], Bh);
                    MMA_BF16(acc[mt][nt], Ah[mt], Bl);
                    MMA_BF16(acc[mt][nt], Al[mt], Bh);
                }
            }
        }
        __syncthreads();
    }

    #pragma unroll
    for (int nt = 0; nt < 8; ++nt) {
        int n = n0 + wn * 64 + nt * 8 + (lane & 3) * 2;
        float2 bv = *(const float2*)&bout[n];
        #pragma unroll
        for (int mt = 0; mt < 2; ++mt) {
            int m = m0 + wm * 32 + mt * 16 + (lane >> 2);
            float2 v0 = make_float2(acc[mt][nt][0] + bv.x, acc[mt][nt][1] + bv.y);
            float2 v1 = make_float2(acc[mt][nt][2] + bv.x, acc[mt][nt][3] + bv.y);
            *(float2*)&C[(size_t)m * V_ + n] = v0;
            *(float2*)&C[(size_t)(m + 8) * V_ + n] = v1;
        }
    }
}

// ---------------- launch (gru_persistent is launch #5 for ncu -s 5) ----------------
extern "C" void kernel_launch(void* const* d_in, const int* in_sizes, int n_in,
                              void* d_out, int out_size) {
    const int*   tokens = (const int*)d_in[0];
    const float* hidden = (const float*)d_in[1];
    const float* emb    = (const float*)d_in[2];
    const float* Wr     = (const float*)d_in[3];
    const float* br     = (const float*)d_in[4];
    const float* Wz     = (const float*)d_in[5];
    const float* bz     = (const float*)d_in[6];
    const float* Wh     = (const float*)d_in[7];
    const float* bh     = (const float*)d_in[8];
    const float* Wout   = (const float*)d_in[9];
    const float* bout   = (const float*)d_in[10];
    float* out = (float*)d_out;

    embed_kernel<<<2048, 256>>>(tokens, emb);            // 1
    init_hidden<<<256, 256>>>(hidden);                   // 2
    pack_weights<<<dim3(32, 32, 4), 256>>>(Wr, Wz, Wh);  // 3
    reset_bar<<<1, 1>>>();                               // 4
    gru_persistent<<<NCTA, 256>>>(br, bz, bh);           // 5  <- profiled
    convert_woutT<<<dim3(1000, 16), 256>>>(Wout);        // 6
    out_gemm_hmma<<<dim3(32, 250), 256>>>(bout, out);    // 7
    copy_hidden<<<256, 256>>>(out + (size_t)S_ * B_ * V_);
}